// round 9
// baseline (speedup 1.0000x reference)
#include <cuda_runtime.h>

// B=32, C=3, H=512, W=512 -> tiles: 32*3*64*64 = 393216
#define N_TILES   393216
#define W_IMG     512
#define TPB       256
#define TILES_PER_BLOCK  (TPB / 4)   // 4 threads per tile (packed row-pair each)

typedef unsigned long long ull;

__device__ __forceinline__ ull pk2(float lo, float hi) {
    ull r; asm("mov.b64 %0,{%1,%2};" : "=l"(r) : "f"(lo), "f"(hi)); return r;
}
__device__ __forceinline__ void upk2(ull p, float& lo, float& hi) {
    asm("mov.b64 {%0,%1},%2;" : "=f"(lo), "=f"(hi) : "l"(p));
}
__device__ __forceinline__ ull fadd2(ull a, ull b) {
    ull r; asm("add.rn.f32x2 %0,%1,%2;" : "=l"(r) : "l"(a), "l"(b)); return r;
}
__device__ __forceinline__ ull fsub2(ull a, ull b) {
    ull r; asm("sub.rn.f32x2 %0,%1,%2;" : "=l"(r) : "l"(a), "l"(b)); return r;
}
__device__ __forceinline__ ull fmul2(ull a, ull b) {
    ull r; asm("mul.rn.f32x2 %0,%1,%2;" : "=l"(r) : "l"(a), "l"(b)); return r;
}
__device__ __forceinline__ ull ffma2(ull a, ull b, ull c) {
    ull r; asm("fma.rn.f32x2 %0,%1,%2,%3;" : "=l"(r) : "l"(a), "l"(b), "l"(c)); return r;
}
// Scalar saturating FMA: clamps result to [0,1]. SASS: FFMA.SAT (fma pipe).
__device__ __forceinline__ float ffma_sat(float a, float b, float c) {
    float r; asm("fma.rn.sat.f32 %0,%1,%2,%3;" : "=f"(r) : "f"(a), "f"(b), "f"(c)); return r;
}
// Direct 64-bit shared load into a packed operand.
__device__ __forceinline__ ull lds64(const ull* p) {
    ull r; asm("ld.shared.b64 %0,[%1];" : "=l"(r) : "l"((size_t)__cvta_generic_to_shared(p))); return r;
}

// Packed constants (row-pair identical).
struct K {
    ull C1, C2, C3, C4, C5, C6, C7;
    ull N1, N2, N5, N7;
};

// Packed 8-point DCT-II (folded 0.5*alpha scaling), butterfly form.
__device__ __forceinline__ void dct8p(ull* t, const K& k) {
    ull s0 = fadd2(t[0], t[7]), s1 = fadd2(t[1], t[6]);
    ull s2 = fadd2(t[2], t[5]), s3 = fadd2(t[3], t[4]);
    ull d0 = fsub2(t[0], t[7]), d1 = fsub2(t[1], t[6]);
    ull d2 = fsub2(t[2], t[5]), d3 = fsub2(t[3], t[4]);
    ull e0 = fadd2(s0, s3), e1 = fadd2(s1, s2);
    ull f0 = fsub2(s0, s3), f1 = fsub2(s1, s2);

    t[0] = fmul2(k.C4, fadd2(e0, e1));
    t[4] = fmul2(k.C4, fsub2(e0, e1));
    t[2] = ffma2(k.C6, f1, fmul2(k.C2, f0));
    t[6] = ffma2(k.N2, f1, fmul2(k.C6, f0));
    t[1] = ffma2(k.C7, d3, ffma2(k.C5, d2, ffma2(k.C3, d1, fmul2(k.C1, d0))));
    t[3] = ffma2(k.N5, d3, ffma2(k.N1, d2, ffma2(k.N7, d1, fmul2(k.C3, d0))));
    t[5] = ffma2(k.C3, d3, ffma2(k.C7, d2, ffma2(k.N1, d1, fmul2(k.C5, d0))));
    t[7] = ffma2(k.N1, d3, ffma2(k.C3, d2, ffma2(k.N5, d1, fmul2(k.C7, d0))));
}

// Packed inverse (transpose matrix; 0.25*idct_alpha folded).
__device__ __forceinline__ void idct8p(ull* t, const K& k) {
    ull a0 = fmul2(k.C4, fadd2(t[0], t[4]));
    ull a1 = fmul2(k.C4, fsub2(t[0], t[4]));
    ull b0 = ffma2(k.C6, t[6], fmul2(k.C2, t[2]));
    ull b1 = ffma2(k.N2, t[6], fmul2(k.C6, t[2]));
    ull E0 = fadd2(a0, b0), E1 = fadd2(a1, b1);
    ull E2 = fsub2(a1, b1), E3 = fsub2(a0, b0);

    ull O0 = ffma2(k.C7, t[7], ffma2(k.C5, t[5], ffma2(k.C3, t[3], fmul2(k.C1, t[1]))));
    ull O1 = ffma2(k.N5, t[7], ffma2(k.N1, t[5], ffma2(k.N7, t[3], fmul2(k.C3, t[1]))));
    ull O2 = ffma2(k.C3, t[7], ffma2(k.C7, t[5], ffma2(k.N1, t[3], fmul2(k.C5, t[1]))));
    ull O3 = ffma2(k.N1, t[7], ffma2(k.C3, t[5], ffma2(k.N5, t[3], fmul2(k.C7, t[1]))));

    t[0] = fadd2(E0, O0);  t[7] = fsub2(E0, O0);
    t[1] = fadd2(E1, O1);  t[6] = fsub2(E1, O1);
    t[2] = fadd2(E2, O2);  t[5] = fsub2(E2, O2);
    t[3] = fadd2(E3, O3);  t[4] = fsub2(E3, O3);
}

// Packed butterfly exchange between P[i] and P[j] across lanes (mask).
#define XSTEPP(I, J, FLAG, MASK) do {                                  \
    ull _s = (FLAG) ? P[I] : P[J];                                     \
    ull _r = __shfl_xor_sync(0xffffffffu, _s, (MASK));                 \
    if (FLAG) P[I] = _r; else P[J] = _r;                               \
} while (0)

// 8x8 transpose on packed row-pairs. Row coord: bit0 = pack-half,
// bit1 = lane bit3, bit2 = lane bit4. Column coord = register index.
__device__ __forceinline__ void xposep(ull P[8], int lane) {
    bool f2 = (lane >> 4) & 1;
    XSTEPP(0, 4, f2, 16);  XSTEPP(1, 5, f2, 16);
    XSTEPP(2, 6, f2, 16);  XSTEPP(3, 7, f2, 16);
    bool f1 = (lane >> 3) & 1;
    XSTEPP(0, 2, f1, 8);   XSTEPP(1, 3, f1, 8);
    XSTEPP(4, 6, f1, 8);   XSTEPP(5, 7, f1, 8);
    // bit0 (pack-half) <-> column bit0: repack halves.
    #pragma unroll
    for (int c = 0; c < 8; c += 2) {
        float a0, a1, b0, b1;
        upk2(P[c], a0, a1);
        upk2(P[c + 1], b0, b1);
        P[c]     = pk2(a0, b0);
        P[c + 1] = pk2(a1, b1);
    }
}

__global__ __launch_bounds__(TPB, 6)
void dct_quant_kernel(const float* __restrict__ in,
                      const float* __restrict__ y_table,
                      const float* __restrict__ c_table,
                      const void*  __restrict__ factor_p,
                      float* __restrict__ out)
{
    // Pre-packed tables: index [ch][u*4 + rr] -> pair over v = (2rr, 2rr+1).
    // sQV = qt (dequant scale), sQI = 127.5/qt (centering folded in).
    __shared__ ull sQV[3][32];
    __shared__ ull sQI[3][32];

    int tid = threadIdx.x;
    {
        int   iv = *(const int*)factor_p;
        float f  = (iv >= 1 && iv <= (1 << 20)) ? (float)iv : *(const float*)factor_p;
        if (tid < 96) {
            int ch = tid / 32;          // 0..2
            int p  = tid & 31;          // u*4 + rr
            int u  = p >> 2;
            int v0 = (p & 3) * 2;
            float sc = (ch == 0) ? f : (0.5f * f);
            const float* tb = (ch == 0) ? y_table : c_table;
            float qa = tb[u * 8 + v0] * sc;
            float qb = tb[u * 8 + v0 + 1] * sc;
            sQV[ch][p] = pk2(qa, qb);
            sQI[ch][p] = pk2(127.5f / qa, 127.5f / qb);
        }
    }
    __syncthreads();

    K k;
    k.C1 = pk2( 0.4903926402016152f,  0.4903926402016152f);
    k.C2 = pk2( 0.4619397662556434f,  0.4619397662556434f);
    k.C3 = pk2( 0.4157348061512726f,  0.4157348061512726f);
    k.C4 = pk2( 0.3535533905932738f,  0.3535533905932738f);
    k.C5 = pk2( 0.2777851165098011f,  0.2777851165098011f);
    k.C6 = pk2( 0.1913417161825449f,  0.1913417161825449f);
    k.C7 = pk2( 0.0975451610080641f,  0.0975451610080641f);
    k.N1 = pk2(-0.4903926402016152f, -0.4903926402016152f);
    k.N2 = pk2(-0.4619397662556434f, -0.4619397662556434f);
    k.N5 = pk2(-0.2777851165098011f, -0.2777851165098011f);
    k.N7 = pk2(-0.0975451610080641f, -0.0975451610080641f);
    // round-half-even magic: |q| <= ~51 << 2^22, so (q+M)-M == rint(q) exactly.
    ull MAGIC = pk2(12582912.0f, 12582912.0f);   // 1.5 * 2^23

    int lane = tid & 31;
    int t  = lane & 7;          // tile within warp
    int rr = (lane >> 3) & 3;   // row-pair index: rows 2rr, 2rr+1

    int tile = (blockIdx.x * (TPB >> 5) + (tid >> 5)) * 8 + t;
    int tw = tile & 63;
    int th = (tile >> 6) & 63;
    int bc = tile >> 12;
    int ch = bc - (bc / 3) * 3;

    // 32-bit flat element offset (max 25.1M elements, fits easily).
    unsigned off = ((unsigned)bc * W_IMG + (unsigned)th * 8 + 2u * rr) * W_IMG + (unsigned)tw * 8;
    const float* src = in + off;

    ull P[8];

    // Load 2 rows, pack pairs. Centering (x*127.5) folded into quant tables.
    {
        float4 a0 = *(const float4*)(src);
        float4 b0 = *(const float4*)(src + 4);
        float4 a1 = *(const float4*)(src + W_IMG);
        float4 b1 = *(const float4*)(src + W_IMG + 4);
        P[0] = pk2(a0.x, a1.x);
        P[1] = pk2(a0.y, a1.y);
        P[2] = pk2(a0.z, a1.z);
        P[3] = pk2(a0.w, a1.w);
        P[4] = pk2(b0.x, b1.x);
        P[5] = pk2(b0.y, b1.y);
        P[6] = pk2(b0.z, b1.z);
        P[7] = pk2(b0.w, b1.w);
    }

    // Forward: DCT over regs, transpose, DCT over regs
    dct8p(P, k);
    xposep(P, lane);            // lane/pack coord = v, regs = x
    dct8p(P, k);                // regs = u; element F[u][v] (unscaled by 127.5)

    // Quantize / dequantize (diff_round: r + (x-r)^3), fully packed.
    // q = F * (127.5/qt); dq = diff_round(q) * qt.
    {
        const ull* qvp = &sQV[ch][rr];
        const ull* qip = &sQI[ch][rr];
        #pragma unroll
        for (int c = 0; c < 8; c++) {
            ull QI = lds64(qip + c * 4);
            ull QV = lds64(qvp + c * 4);
            ull q  = fmul2(P[c], QI);
            ull rp = fsub2(fadd2(q, MAGIC), MAGIC);   // rint, round-half-even
            ull e  = fsub2(q, rp);
            ull dr = ffma2(fmul2(e, e), e, rp);
            P[c] = fmul2(dr, QV);
        }
    }

    // Inverse: IDCT over regs, transpose, IDCT over regs
    idct8p(P, k);               // regs = x spatial
    xposep(P, lane);            // lane/pack coord = x, regs = v
    idct8p(P, k);               // regs/pack = spatial rows

    // Final: clip(x+127.5,0,255)/127.5-1 == 2*sat(x/255 + 0.5) - 1.
    float* dst = out + off;
    const float inv255 = 1.0f / 255.0f;
    float4 w0, w1, w2, w3;
    {
        float x0, x1;
        upk2(P[0], x0, x1);
        w0.x = fmaf(ffma_sat(x0, inv255, 0.5f), 2.0f, -1.0f);
        w2.x = fmaf(ffma_sat(x1, inv255, 0.5f), 2.0f, -1.0f);
        upk2(P[1], x0, x1);
        w0.y = fmaf(ffma_sat(x0, inv255, 0.5f), 2.0f, -1.0f);
        w2.y = fmaf(ffma_sat(x1, inv255, 0.5f), 2.0f, -1.0f);
        upk2(P[2], x0, x1);
        w0.z = fmaf(ffma_sat(x0, inv255, 0.5f), 2.0f, -1.0f);
        w2.z = fmaf(ffma_sat(x1, inv255, 0.5f), 2.0f, -1.0f);
        upk2(P[3], x0, x1);
        w0.w = fmaf(ffma_sat(x0, inv255, 0.5f), 2.0f, -1.0f);
        w2.w = fmaf(ffma_sat(x1, inv255, 0.5f), 2.0f, -1.0f);
        upk2(P[4], x0, x1);
        w1.x = fmaf(ffma_sat(x0, inv255, 0.5f), 2.0f, -1.0f);
        w3.x = fmaf(ffma_sat(x1, inv255, 0.5f), 2.0f, -1.0f);
        upk2(P[5], x0, x1);
        w1.y = fmaf(ffma_sat(x0, inv255, 0.5f), 2.0f, -1.0f);
        w3.y = fmaf(ffma_sat(x1, inv255, 0.5f), 2.0f, -1.0f);
        upk2(P[6], x0, x1);
        w1.z = fmaf(ffma_sat(x0, inv255, 0.5f), 2.0f, -1.0f);
        w3.z = fmaf(ffma_sat(x1, inv255, 0.5f), 2.0f, -1.0f);
        upk2(P[7], x0, x1);
        w1.w = fmaf(ffma_sat(x0, inv255, 0.5f), 2.0f, -1.0f);
        w3.w = fmaf(ffma_sat(x1, inv255, 0.5f), 2.0f, -1.0f);
    }
    *(float4*)(dst)             = w0;
    *(float4*)(dst + 4)         = w1;
    *(float4*)(dst + W_IMG)     = w2;
    *(float4*)(dst + W_IMG + 4) = w3;
}

extern "C" void kernel_launch(void* const* d_in, const int* in_sizes, int n_in,
                              void* d_out, int out_size)
{
    // metadata order: input, dct_tensor, dct_scale, idct_tensor, idct_alpha,
    //                 y_table, c_table, factor
    const float* in = (const float*)d_in[0];
    const float* yt = (const float*)d_in[5];
    const float* ct = (const float*)d_in[6];
    const void*  fp = d_in[7];
    float* outp = (float*)d_out;

    dim3 grid(N_TILES / TILES_PER_BLOCK);
    dct_quant_kernel<<<grid, TPB>>>(in, yt, ct, fp, outp);
}

// round 11
// speedup vs baseline: 1.0109x; 1.0109x over previous
#include <cuda_runtime.h>

// B=32, C=3, H=512, W=512 -> tiles: 32*3*64*64 = 393216
#define N_TILES   393216
#define W_IMG     512
#define TPB       256
#define TILES_PER_BLOCK  (TPB / 4)   // 4 threads per tile (packed row-pair each)

typedef unsigned long long ull;

__device__ __forceinline__ ull pk2(float lo, float hi) {
    ull r; asm("mov.b64 %0,{%1,%2};" : "=l"(r) : "f"(lo), "f"(hi)); return r;
}
__device__ __forceinline__ void upk2(ull p, float& lo, float& hi) {
    asm("mov.b64 {%0,%1},%2;" : "=f"(lo), "=f"(hi) : "l"(p));
}
__device__ __forceinline__ ull fadd2(ull a, ull b) {
    ull r; asm("add.rn.f32x2 %0,%1,%2;" : "=l"(r) : "l"(a), "l"(b)); return r;
}
__device__ __forceinline__ ull fsub2(ull a, ull b) {
    ull r; asm("sub.rn.f32x2 %0,%1,%2;" : "=l"(r) : "l"(a), "l"(b)); return r;
}
__device__ __forceinline__ ull fmul2(ull a, ull b) {
    ull r; asm("mul.rn.f32x2 %0,%1,%2;" : "=l"(r) : "l"(a), "l"(b)); return r;
}
__device__ __forceinline__ ull ffma2(ull a, ull b, ull c) {
    ull r; asm("fma.rn.f32x2 %0,%1,%2,%3;" : "=l"(r) : "l"(a), "l"(b), "l"(c)); return r;
}
// Scalar saturating FMA: clamps result to [0,1]. SASS: FFMA.SAT (fma pipe).
__device__ __forceinline__ float ffma_sat(float a, float b, float c) {
    float r; asm("fma.rn.sat.f32 %0,%1,%2,%3;" : "=f"(r) : "f"(a), "f"(b), "f"(c)); return r;
}
// One 16B shared load -> two packed 64-bit operands (LDS.128).
__device__ __forceinline__ void lds128(const void* p, ull& a, ull& b) {
    asm("ld.shared.v2.b64 {%0,%1},[%2];"
        : "=l"(a), "=l"(b)
        : "l"((size_t)__cvta_generic_to_shared(p)));
}

// Packed constants (row-pair identical).
struct K {
    ull C1, C2, C3, C4, C5, C6, C7;
    ull N1, N2, N5, N7;
};

// Packed 8-point DCT-II (folded 0.5*alpha scaling), butterfly form.
__device__ __forceinline__ void dct8p(ull* t, const K& k) {
    ull s0 = fadd2(t[0], t[7]), s1 = fadd2(t[1], t[6]);
    ull s2 = fadd2(t[2], t[5]), s3 = fadd2(t[3], t[4]);
    ull d0 = fsub2(t[0], t[7]), d1 = fsub2(t[1], t[6]);
    ull d2 = fsub2(t[2], t[5]), d3 = fsub2(t[3], t[4]);
    ull e0 = fadd2(s0, s3), e1 = fadd2(s1, s2);
    ull f0 = fsub2(s0, s3), f1 = fsub2(s1, s2);

    t[0] = fmul2(k.C4, fadd2(e0, e1));
    t[4] = fmul2(k.C4, fsub2(e0, e1));
    t[2] = ffma2(k.C6, f1, fmul2(k.C2, f0));
    t[6] = ffma2(k.N2, f1, fmul2(k.C6, f0));
    t[1] = ffma2(k.C7, d3, ffma2(k.C5, d2, ffma2(k.C3, d1, fmul2(k.C1, d0))));
    t[3] = ffma2(k.N5, d3, ffma2(k.N1, d2, ffma2(k.N7, d1, fmul2(k.C3, d0))));
    t[5] = ffma2(k.C3, d3, ffma2(k.C7, d2, ffma2(k.N1, d1, fmul2(k.C5, d0))));
    t[7] = ffma2(k.N1, d3, ffma2(k.C3, d2, ffma2(k.N5, d1, fmul2(k.C7, d0))));
}

// Packed inverse (transpose matrix; 0.25*idct_alpha folded).
__device__ __forceinline__ void idct8p(ull* t, const K& k) {
    ull a0 = fmul2(k.C4, fadd2(t[0], t[4]));
    ull a1 = fmul2(k.C4, fsub2(t[0], t[4]));
    ull b0 = ffma2(k.C6, t[6], fmul2(k.C2, t[2]));
    ull b1 = ffma2(k.N2, t[6], fmul2(k.C6, t[2]));
    ull E0 = fadd2(a0, b0), E1 = fadd2(a1, b1);
    ull E2 = fsub2(a1, b1), E3 = fsub2(a0, b0);

    ull O0 = ffma2(k.C7, t[7], ffma2(k.C5, t[5], ffma2(k.C3, t[3], fmul2(k.C1, t[1]))));
    ull O1 = ffma2(k.N5, t[7], ffma2(k.N1, t[5], ffma2(k.N7, t[3], fmul2(k.C3, t[1]))));
    ull O2 = ffma2(k.C3, t[7], ffma2(k.C7, t[5], ffma2(k.N1, t[3], fmul2(k.C5, t[1]))));
    ull O3 = ffma2(k.N1, t[7], ffma2(k.C3, t[5], ffma2(k.N5, t[3], fmul2(k.C7, t[1]))));

    t[0] = fadd2(E0, O0);  t[7] = fsub2(E0, O0);
    t[1] = fadd2(E1, O1);  t[6] = fsub2(E1, O1);
    t[2] = fadd2(E2, O2);  t[5] = fsub2(E2, O2);
    t[3] = fadd2(E3, O3);  t[4] = fsub2(E3, O3);
}

// Packed butterfly exchange between P[i] and P[j] across lanes (mask).
#define XSTEPP(I, J, FLAG, MASK) do {                                  \
    ull _s = (FLAG) ? P[I] : P[J];                                     \
    ull _r = __shfl_xor_sync(0xffffffffu, _s, (MASK));                 \
    if (FLAG) P[I] = _r; else P[J] = _r;                               \
} while (0)

// 8x8 transpose on packed row-pairs. Row coord: bit0 = pack-half,
// bit1 = lane bit3, bit2 = lane bit4. Column coord = register index.
__device__ __forceinline__ void xposep(ull P[8], int lane) {
    bool f2 = (lane >> 4) & 1;
    XSTEPP(0, 4, f2, 16);  XSTEPP(1, 5, f2, 16);
    XSTEPP(2, 6, f2, 16);  XSTEPP(3, 7, f2, 16);
    bool f1 = (lane >> 3) & 1;
    XSTEPP(0, 2, f1, 8);   XSTEPP(1, 3, f1, 8);
    XSTEPP(4, 6, f1, 8);   XSTEPP(5, 7, f1, 8);
    // bit0 (pack-half) <-> column bit0: repack halves.
    #pragma unroll
    for (int c = 0; c < 8; c += 2) {
        float a0, a1, b0, b1;
        upk2(P[c], a0, a1);
        upk2(P[c + 1], b0, b1);
        P[c]     = pk2(a0, b0);
        P[c + 1] = pk2(a1, b1);
    }
}

__global__ __launch_bounds__(TPB, 6)
void dct_quant_kernel(const float* __restrict__ in,
                      const float* __restrict__ y_table,
                      const float* __restrict__ c_table,
                      const void*  __restrict__ factor_p,
                      float* __restrict__ out)
{
    // Combined table: [ch][u*4 + rr] -> { packed (qv0,qv1), packed (qi0,qi1) }
    // where v = (2rr, 2rr+1). qv = qt (dequant scale), qi = 127.5/qt
    // (centering folded in). One LDS.128 yields both packed operands.
    __shared__ ulonglong2 sQ[3][32];

    int tid = threadIdx.x;
    {
        int   iv = *(const int*)factor_p;
        float f  = (iv >= 1 && iv <= (1 << 20)) ? (float)iv : *(const float*)factor_p;
        if (tid < 96) {
            int ch = tid / 32;          // 0..2
            int p  = tid & 31;          // u*4 + rr
            int u  = p >> 2;
            int v0 = (p & 3) * 2;
            float sc = (ch == 0) ? f : (0.5f * f);
            const float* tb = (ch == 0) ? y_table : c_table;
            float qa = tb[u * 8 + v0] * sc;
            float qb = tb[u * 8 + v0 + 1] * sc;
            ulonglong2 e;
            e.x = pk2(qa, qb);
            e.y = pk2(127.5f / qa, 127.5f / qb);
            sQ[ch][p] = e;
        }
    }
    __syncthreads();

    K k;
    k.C1 = pk2( 0.4903926402016152f,  0.4903926402016152f);
    k.C2 = pk2( 0.4619397662556434f,  0.4619397662556434f);
    k.C3 = pk2( 0.4157348061512726f,  0.4157348061512726f);
    k.C4 = pk2( 0.3535533905932738f,  0.3535533905932738f);
    k.C5 = pk2( 0.2777851165098011f,  0.2777851165098011f);
    k.C6 = pk2( 0.1913417161825449f,  0.1913417161825449f);
    k.C7 = pk2( 0.0975451610080641f,  0.0975451610080641f);
    k.N1 = pk2(-0.4903926402016152f, -0.4903926402016152f);
    k.N2 = pk2(-0.4619397662556434f, -0.4619397662556434f);
    k.N5 = pk2(-0.2777851165098011f, -0.2777851165098011f);
    k.N7 = pk2(-0.0975451610080641f, -0.0975451610080641f);
    // round-half-even magic: |q| <= ~51 << 2^22, so (q+M)-M == rint(q) exactly.
    ull MAGIC = pk2(12582912.0f, 12582912.0f);   // 1.5 * 2^23

    int lane = tid & 31;
    int t  = lane & 7;          // tile within warp
    int rr = (lane >> 3) & 3;   // row-pair index: rows 2rr, 2rr+1

    int tile = (blockIdx.x * (TPB >> 5) + (tid >> 5)) * 8 + t;
    int tw = tile & 63;
    int th = (tile >> 6) & 63;
    int bc = tile >> 12;
    int ch = bc - (bc / 3) * 3;

    // 32-bit flat element offset (max 25.1M elements, fits easily).
    unsigned off = ((unsigned)bc * W_IMG + (unsigned)th * 8 + 2u * rr) * W_IMG + (unsigned)tw * 8;
    const float* src = in + off;

    ull P[8];

    // Load 2 rows, pack pairs. Centering (x*127.5) folded into quant tables.
    {
        float4 a0 = *(const float4*)(src);
        float4 b0 = *(const float4*)(src + 4);
        float4 a1 = *(const float4*)(src + W_IMG);
        float4 b1 = *(const float4*)(src + W_IMG + 4);
        P[0] = pk2(a0.x, a1.x);
        P[1] = pk2(a0.y, a1.y);
        P[2] = pk2(a0.z, a1.z);
        P[3] = pk2(a0.w, a1.w);
        P[4] = pk2(b0.x, b1.x);
        P[5] = pk2(b0.y, b1.y);
        P[6] = pk2(b0.z, b1.z);
        P[7] = pk2(b0.w, b1.w);
    }

    // Forward: DCT over regs, transpose, DCT over regs
    dct8p(P, k);
    xposep(P, lane);            // lane/pack coord = v, regs = x
    dct8p(P, k);                // regs = u; element F[u][v] (unscaled by 127.5)

    // Quantize / dequantize (diff_round: r + (x-r)^3), fully packed.
    // q = F * (127.5/qt); dq = diff_round(q) * qt.
    {
        const ulonglong2* qp = &sQ[ch][rr];
        #pragma unroll
        for (int c = 0; c < 8; c++) {
            ull QV, QI;
            lds128(qp + c * 4, QV, QI);
            ull q  = fmul2(P[c], QI);
            ull rp = fsub2(fadd2(q, MAGIC), MAGIC);   // rint, round-half-even
            ull e  = fsub2(q, rp);
            ull dr = ffma2(fmul2(e, e), e, rp);
            P[c] = fmul2(dr, QV);
        }
    }

    // Inverse: IDCT over regs, transpose, IDCT over regs
    idct8p(P, k);               // regs = x spatial
    xposep(P, lane);            // lane/pack coord = x, regs = v
    idct8p(P, k);               // regs/pack = spatial rows

    // Final: clip(x+127.5,0,255)/127.5-1 == 2*sat(x/255 + 0.5) - 1.
    float* dst = out + off;
    const float inv255 = 1.0f / 255.0f;
    float4 w0, w1, w2, w3;
    {
        float x0, x1;
        upk2(P[0], x0, x1);
        w0.x = fmaf(ffma_sat(x0, inv255, 0.5f), 2.0f, -1.0f);
        w2.x = fmaf(ffma_sat(x1, inv255, 0.5f), 2.0f, -1.0f);
        upk2(P[1], x0, x1);
        w0.y = fmaf(ffma_sat(x0, inv255, 0.5f), 2.0f, -1.0f);
        w2.y = fmaf(ffma_sat(x1, inv255, 0.5f), 2.0f, -1.0f);
        upk2(P[2], x0, x1);
        w0.z = fmaf(ffma_sat(x0, inv255, 0.5f), 2.0f, -1.0f);
        w2.z = fmaf(ffma_sat(x1, inv255, 0.5f), 2.0f, -1.0f);
        upk2(P[3], x0, x1);
        w0.w = fmaf(ffma_sat(x0, inv255, 0.5f), 2.0f, -1.0f);
        w2.w = fmaf(ffma_sat(x1, inv255, 0.5f), 2.0f, -1.0f);
        upk2(P[4], x0, x1);
        w1.x = fmaf(ffma_sat(x0, inv255, 0.5f), 2.0f, -1.0f);
        w3.x = fmaf(ffma_sat(x1, inv255, 0.5f), 2.0f, -1.0f);
        upk2(P[5], x0, x1);
        w1.y = fmaf(ffma_sat(x0, inv255, 0.5f), 2.0f, -1.0f);
        w3.y = fmaf(ffma_sat(x1, inv255, 0.5f), 2.0f, -1.0f);
        upk2(P[6], x0, x1);
        w1.z = fmaf(ffma_sat(x0, inv255, 0.5f), 2.0f, -1.0f);
        w3.z = fmaf(ffma_sat(x1, inv255, 0.5f), 2.0f, -1.0f);
        upk2(P[7], x0, x1);
        w1.w = fmaf(ffma_sat(x0, inv255, 0.5f), 2.0f, -1.0f);
        w3.w = fmaf(ffma_sat(x1, inv255, 0.5f), 2.0f, -1.0f);
    }
    *(float4*)(dst)             = w0;
    *(float4*)(dst + 4)         = w1;
    *(float4*)(dst + W_IMG)     = w2;
    *(float4*)(dst + W_IMG + 4) = w3;
}

extern "C" void kernel_launch(void* const* d_in, const int* in_sizes, int n_in,
                              void* d_out, int out_size)
{
    // metadata order: input, dct_tensor, dct_scale, idct_tensor, idct_alpha,
    //                 y_table, c_table, factor
    const float* in = (const float*)d_in[0];
    const float* yt = (const float*)d_in[5];
    const float* ct = (const float*)d_in[6];
    const void*  fp = d_in[7];
    float* outp = (float*)d_out;

    dim3 grid(N_TILES / TILES_PER_BLOCK);
    dct_quant_kernel<<<grid, TPB>>>(in, yt, ct, fp, outp);
}

// round 12
// speedup vs baseline: 1.0649x; 1.0534x over previous
#include <cuda_runtime.h>

// B=32, C=3, H=512, W=512 -> tiles: 32*3*64*64 = 393216
#define N_TILES   393216
#define W_IMG     512
#define TPB       256
// 4 threads per tile, 2 tiles per thread -> warp covers 16 tiles, block 128.
#define TILES_PER_BLOCK  ((TPB / 4) * 2)

typedef unsigned long long ull;

__device__ __forceinline__ ull pk2(float lo, float hi) {
    ull r; asm("mov.b64 %0,{%1,%2};" : "=l"(r) : "f"(lo), "f"(hi)); return r;
}
__device__ __forceinline__ void upk2(ull p, float& lo, float& hi) {
    asm("mov.b64 {%0,%1},%2;" : "=f"(lo), "=f"(hi) : "l"(p));
}
__device__ __forceinline__ ull fadd2(ull a, ull b) {
    ull r; asm("add.rn.f32x2 %0,%1,%2;" : "=l"(r) : "l"(a), "l"(b)); return r;
}
__device__ __forceinline__ ull fsub2(ull a, ull b) {
    ull r; asm("sub.rn.f32x2 %0,%1,%2;" : "=l"(r) : "l"(a), "l"(b)); return r;
}
__device__ __forceinline__ ull fmul2(ull a, ull b) {
    ull r; asm("mul.rn.f32x2 %0,%1,%2;" : "=l"(r) : "l"(a), "l"(b)); return r;
}
__device__ __forceinline__ ull ffma2(ull a, ull b, ull c) {
    ull r; asm("fma.rn.f32x2 %0,%1,%2,%3;" : "=l"(r) : "l"(a), "l"(b), "l"(c)); return r;
}
// Scalar saturating FMA: clamps result to [0,1]. SASS: FFMA.SAT (fma pipe).
__device__ __forceinline__ float ffma_sat(float a, float b, float c) {
    float r; asm("fma.rn.sat.f32 %0,%1,%2,%3;" : "=f"(r) : "f"(a), "f"(b), "f"(c)); return r;
}
// One 16B shared load -> two packed 64-bit operands (LDS.128).
__device__ __forceinline__ void lds128(const void* p, ull& a, ull& b) {
    asm("ld.shared.v2.b64 {%0,%1},[%2];"
        : "=l"(a), "=l"(b)
        : "l"((size_t)__cvta_generic_to_shared(p)));
}

// Packed constants (row-pair identical).
struct K {
    ull C1, C2, C3, C4, C5, C6, C7;
    ull N1, N2, N5, N7;
};

// Packed 8-point DCT-II (folded 0.5*alpha scaling), butterfly form.
__device__ __forceinline__ void dct8p(ull* t, const K& k) {
    ull s0 = fadd2(t[0], t[7]), s1 = fadd2(t[1], t[6]);
    ull s2 = fadd2(t[2], t[5]), s3 = fadd2(t[3], t[4]);
    ull d0 = fsub2(t[0], t[7]), d1 = fsub2(t[1], t[6]);
    ull d2 = fsub2(t[2], t[5]), d3 = fsub2(t[3], t[4]);
    ull e0 = fadd2(s0, s3), e1 = fadd2(s1, s2);
    ull f0 = fsub2(s0, s3), f1 = fsub2(s1, s2);

    t[0] = fmul2(k.C4, fadd2(e0, e1));
    t[4] = fmul2(k.C4, fsub2(e0, e1));
    t[2] = ffma2(k.C6, f1, fmul2(k.C2, f0));
    t[6] = ffma2(k.N2, f1, fmul2(k.C6, f0));
    t[1] = ffma2(k.C7, d3, ffma2(k.C5, d2, ffma2(k.C3, d1, fmul2(k.C1, d0))));
    t[3] = ffma2(k.N5, d3, ffma2(k.N1, d2, ffma2(k.N7, d1, fmul2(k.C3, d0))));
    t[5] = ffma2(k.C3, d3, ffma2(k.C7, d2, ffma2(k.N1, d1, fmul2(k.C5, d0))));
    t[7] = ffma2(k.N1, d3, ffma2(k.C3, d2, ffma2(k.N5, d1, fmul2(k.C7, d0))));
}

// Packed inverse (transpose matrix; 0.25*idct_alpha folded).
__device__ __forceinline__ void idct8p(ull* t, const K& k) {
    ull a0 = fmul2(k.C4, fadd2(t[0], t[4]));
    ull a1 = fmul2(k.C4, fsub2(t[0], t[4]));
    ull b0 = ffma2(k.C6, t[6], fmul2(k.C2, t[2]));
    ull b1 = ffma2(k.N2, t[6], fmul2(k.C6, t[2]));
    ull E0 = fadd2(a0, b0), E1 = fadd2(a1, b1);
    ull E2 = fsub2(a1, b1), E3 = fsub2(a0, b0);

    ull O0 = ffma2(k.C7, t[7], ffma2(k.C5, t[5], ffma2(k.C3, t[3], fmul2(k.C1, t[1]))));
    ull O1 = ffma2(k.N5, t[7], ffma2(k.N1, t[5], ffma2(k.N7, t[3], fmul2(k.C3, t[1]))));
    ull O2 = ffma2(k.C3, t[7], ffma2(k.C7, t[5], ffma2(k.N1, t[3], fmul2(k.C5, t[1]))));
    ull O3 = ffma2(k.N1, t[7], ffma2(k.C3, t[5], ffma2(k.N5, t[3], fmul2(k.C7, t[1]))));

    t[0] = fadd2(E0, O0);  t[7] = fsub2(E0, O0);
    t[1] = fadd2(E1, O1);  t[6] = fsub2(E1, O1);
    t[2] = fadd2(E2, O2);  t[5] = fsub2(E2, O2);
    t[3] = fadd2(E3, O3);  t[4] = fsub2(E3, O3);
}

// Packed butterfly exchange between P[i] and P[j] across lanes (mask).
#define XSTEPP(P, I, J, FLAG, MASK) do {                               \
    ull _s = (FLAG) ? P[I] : P[J];                                     \
    ull _r = __shfl_xor_sync(0xffffffffu, _s, (MASK));                 \
    if (FLAG) P[I] = _r; else P[J] = _r;                               \
} while (0)

// 8x8 transpose on packed row-pairs, two tiles interleaved for ILP.
// Row coord: bit0 = pack-half, bit1 = lane bit3, bit2 = lane bit4.
__device__ __forceinline__ void xposep2(ull PA[8], ull PB[8], int lane) {
    bool f2 = (lane >> 4) & 1;
    XSTEPP(PA, 0, 4, f2, 16);  XSTEPP(PB, 0, 4, f2, 16);
    XSTEPP(PA, 1, 5, f2, 16);  XSTEPP(PB, 1, 5, f2, 16);
    XSTEPP(PA, 2, 6, f2, 16);  XSTEPP(PB, 2, 6, f2, 16);
    XSTEPP(PA, 3, 7, f2, 16);  XSTEPP(PB, 3, 7, f2, 16);
    bool f1 = (lane >> 3) & 1;
    XSTEPP(PA, 0, 2, f1, 8);   XSTEPP(PB, 0, 2, f1, 8);
    XSTEPP(PA, 1, 3, f1, 8);   XSTEPP(PB, 1, 3, f1, 8);
    XSTEPP(PA, 4, 6, f1, 8);   XSTEPP(PB, 4, 6, f1, 8);
    XSTEPP(PA, 5, 7, f1, 8);   XSTEPP(PB, 5, 7, f1, 8);
    // bit0 (pack-half) <-> column bit0: repack halves.
    #pragma unroll
    for (int c = 0; c < 8; c += 2) {
        float a0, a1, b0, b1;
        upk2(PA[c], a0, a1);
        upk2(PA[c + 1], b0, b1);
        PA[c]     = pk2(a0, b0);
        PA[c + 1] = pk2(a1, b1);
        upk2(PB[c], a0, a1);
        upk2(PB[c + 1], b0, b1);
        PB[c]     = pk2(a0, b0);
        PB[c + 1] = pk2(a1, b1);
    }
}

__device__ __forceinline__ void load_tile(const float* src, ull P[8]) {
    float4 a0 = *(const float4*)(src);
    float4 b0 = *(const float4*)(src + 4);
    float4 a1 = *(const float4*)(src + W_IMG);
    float4 b1 = *(const float4*)(src + W_IMG + 4);
    P[0] = pk2(a0.x, a1.x);
    P[1] = pk2(a0.y, a1.y);
    P[2] = pk2(a0.z, a1.z);
    P[3] = pk2(a0.w, a1.w);
    P[4] = pk2(b0.x, b1.x);
    P[5] = pk2(b0.y, b1.y);
    P[6] = pk2(b0.z, b1.z);
    P[7] = pk2(b0.w, b1.w);
}

__device__ __forceinline__ void store_tile(float* dst, ull P[8]) {
    const float inv255 = 1.0f / 255.0f;
    float4 w0, w1, w2, w3;
    float x0, x1;
    upk2(P[0], x0, x1);
    w0.x = fmaf(ffma_sat(x0, inv255, 0.5f), 2.0f, -1.0f);
    w2.x = fmaf(ffma_sat(x1, inv255, 0.5f), 2.0f, -1.0f);
    upk2(P[1], x0, x1);
    w0.y = fmaf(ffma_sat(x0, inv255, 0.5f), 2.0f, -1.0f);
    w2.y = fmaf(ffma_sat(x1, inv255, 0.5f), 2.0f, -1.0f);
    upk2(P[2], x0, x1);
    w0.z = fmaf(ffma_sat(x0, inv255, 0.5f), 2.0f, -1.0f);
    w2.z = fmaf(ffma_sat(x1, inv255, 0.5f), 2.0f, -1.0f);
    upk2(P[3], x0, x1);
    w0.w = fmaf(ffma_sat(x0, inv255, 0.5f), 2.0f, -1.0f);
    w2.w = fmaf(ffma_sat(x1, inv255, 0.5f), 2.0f, -1.0f);
    upk2(P[4], x0, x1);
    w1.x = fmaf(ffma_sat(x0, inv255, 0.5f), 2.0f, -1.0f);
    w3.x = fmaf(ffma_sat(x1, inv255, 0.5f), 2.0f, -1.0f);
    upk2(P[5], x0, x1);
    w1.y = fmaf(ffma_sat(x0, inv255, 0.5f), 2.0f, -1.0f);
    w3.y = fmaf(ffma_sat(x1, inv255, 0.5f), 2.0f, -1.0f);
    upk2(P[6], x0, x1);
    w1.z = fmaf(ffma_sat(x0, inv255, 0.5f), 2.0f, -1.0f);
    w3.z = fmaf(ffma_sat(x1, inv255, 0.5f), 2.0f, -1.0f);
    upk2(P[7], x0, x1);
    w1.w = fmaf(ffma_sat(x0, inv255, 0.5f), 2.0f, -1.0f);
    w3.w = fmaf(ffma_sat(x1, inv255, 0.5f), 2.0f, -1.0f);
    *(float4*)(dst)             = w0;
    *(float4*)(dst + 4)         = w1;
    *(float4*)(dst + W_IMG)     = w2;
    *(float4*)(dst + W_IMG + 4) = w3;
}

__global__ __launch_bounds__(TPB, 3)
void dct_quant_kernel(const float* __restrict__ in,
                      const float* __restrict__ y_table,
                      const float* __restrict__ c_table,
                      const void*  __restrict__ factor_p,
                      float* __restrict__ out)
{
    // Combined table: [ch][u*4 + rr] -> { packed (qv0,qv1), packed (qi0,qi1) }
    // where v = (2rr, 2rr+1). qv = qt (dequant scale), qi = 127.5/qt
    // (centering folded in). One LDS.128 yields both packed operands.
    __shared__ ulonglong2 sQ[3][32];

    int tid = threadIdx.x;
    {
        int   iv = *(const int*)factor_p;
        float f  = (iv >= 1 && iv <= (1 << 20)) ? (float)iv : *(const float*)factor_p;
        if (tid < 96) {
            int ch = tid / 32;          // 0..2
            int p  = tid & 31;          // u*4 + rr
            int u  = p >> 2;
            int v0 = (p & 3) * 2;
            float sc = (ch == 0) ? f : (0.5f * f);
            const float* tb = (ch == 0) ? y_table : c_table;
            float qa = tb[u * 8 + v0] * sc;
            float qb = tb[u * 8 + v0 + 1] * sc;
            ulonglong2 e;
            e.x = pk2(qa, qb);
            e.y = pk2(127.5f / qa, 127.5f / qb);
            sQ[ch][p] = e;
        }
    }
    __syncthreads();

    K k;
    k.C1 = pk2( 0.4903926402016152f,  0.4903926402016152f);
    k.C2 = pk2( 0.4619397662556434f,  0.4619397662556434f);
    k.C3 = pk2( 0.4157348061512726f,  0.4157348061512726f);
    k.C4 = pk2( 0.3535533905932738f,  0.3535533905932738f);
    k.C5 = pk2( 0.2777851165098011f,  0.2777851165098011f);
    k.C6 = pk2( 0.1913417161825449f,  0.1913417161825449f);
    k.C7 = pk2( 0.0975451610080641f,  0.0975451610080641f);
    k.N1 = pk2(-0.4903926402016152f, -0.4903926402016152f);
    k.N2 = pk2(-0.4619397662556434f, -0.4619397662556434f);
    k.N5 = pk2(-0.2777851165098011f, -0.2777851165098011f);
    k.N7 = pk2(-0.0975451610080641f, -0.0975451610080641f);
    // round-half-even magic: |q| <= ~51 << 2^22, so (q+M)-M == rint(q) exactly.
    ull MAGIC = pk2(12582912.0f, 12582912.0f);   // 1.5 * 2^23

    int lane = tid & 31;
    int t  = lane & 7;          // first tile within the warp's 16-tile group
    int rr = (lane >> 3) & 3;   // row-pair index: rows 2rr, 2rr+1

    // Warp covers 16 consecutive tiles (same row of blocks, same channel):
    // thread handles tiles gbase+t and gbase+t+8.
    int gbase = (blockIdx.x * (TPB >> 5) + (tid >> 5)) * 16;
    int tile = gbase + t;
    int tw = tile & 63;
    int th = (tile >> 6) & 63;
    int bc = tile >> 12;
    int ch = bc - (bc / 3) * 3;

    // 32-bit flat element offset. Second tile = +8 tiles in w = +64 floats.
    unsigned off = ((unsigned)bc * W_IMG + (unsigned)th * 8 + 2u * rr) * W_IMG + (unsigned)tw * 8;
    const float* srcA = in + off;
    const float* srcB = srcA + 64;

    ull PA[8], PB[8];

    // Issue all 8 global loads back-to-back (MLP=8, one latency window).
    load_tile(srcA, PA);
    load_tile(srcB, PB);

    // Forward: DCT, transpose, DCT — two independent chains interleaved.
    dct8p(PA, k);  dct8p(PB, k);
    xposep2(PA, PB, lane);        // lane/pack coord = v, regs = x
    dct8p(PA, k);  dct8p(PB, k);  // regs = u; F[u][v] (unscaled by 127.5)

    // Quantize / dequantize (diff_round: r + (x-r)^3), fully packed.
    // Same table entry serves both tiles: one LDS.128 per coefficient pair.
    {
        const ulonglong2* qp = &sQ[ch][rr];
        #pragma unroll
        for (int c = 0; c < 8; c++) {
            ull QV, QI;
            lds128(qp + c * 4, QV, QI);
            ull qA  = fmul2(PA[c], QI);
            ull qB  = fmul2(PB[c], QI);
            ull rA  = fsub2(fadd2(qA, MAGIC), MAGIC);  // rint, round-half-even
            ull rB  = fsub2(fadd2(qB, MAGIC), MAGIC);
            ull eA  = fsub2(qA, rA);
            ull eB  = fsub2(qB, rB);
            ull dA  = ffma2(fmul2(eA, eA), eA, rA);
            ull dB  = ffma2(fmul2(eB, eB), eB, rB);
            PA[c] = fmul2(dA, QV);
            PB[c] = fmul2(dB, QV);
        }
    }

    // Inverse: IDCT, transpose, IDCT.
    idct8p(PA, k);  idct8p(PB, k);   // regs = x spatial
    xposep2(PA, PB, lane);           // lane/pack coord = x, regs = v
    idct8p(PA, k);  idct8p(PB, k);   // regs/pack = spatial rows

    // Final: clip(x+127.5,0,255)/127.5-1 == 2*sat(x/255 + 0.5) - 1.
    store_tile(out + off, PA);
    store_tile(out + off + 64, PB);
}

extern "C" void kernel_launch(void* const* d_in, const int* in_sizes, int n_in,
                              void* d_out, int out_size)
{
    // metadata order: input, dct_tensor, dct_scale, idct_tensor, idct_alpha,
    //                 y_table, c_table, factor
    const float* in = (const float*)d_in[0];
    const float* yt = (const float*)d_in[5];
    const float* ct = (const float*)d_in[6];
    const void*  fp = d_in[7];
    float* outp = (float*)d_out;

    dim3 grid(N_TILES / TILES_PER_BLOCK);
    dct_quant_kernel<<<grid, TPB>>>(in, yt, ct, fp, outp);
}

// round 13
// speedup vs baseline: 1.1105x; 1.0428x over previous
#include <cuda_runtime.h>

// B=32, C=3, H=512, W=512 -> tiles: 32*3*64*64 = 393216
#define N_TILES   393216
#define W_IMG     512
#define TPB       128
// 4 threads per tile, 2 tiles per thread -> warp covers 16 tiles, block 64.
#define TILES_PER_BLOCK  ((TPB / 4) * 2)

typedef unsigned long long ull;

__device__ __forceinline__ ull pk2(float lo, float hi) {
    ull r; asm("mov.b64 %0,{%1,%2};" : "=l"(r) : "f"(lo), "f"(hi)); return r;
}
__device__ __forceinline__ void upk2(ull p, float& lo, float& hi) {
    asm("mov.b64 {%0,%1},%2;" : "=f"(lo), "=f"(hi) : "l"(p));
}
__device__ __forceinline__ ull fadd2(ull a, ull b) {
    ull r; asm("add.rn.f32x2 %0,%1,%2;" : "=l"(r) : "l"(a), "l"(b)); return r;
}
__device__ __forceinline__ ull fsub2(ull a, ull b) {
    ull r; asm("sub.rn.f32x2 %0,%1,%2;" : "=l"(r) : "l"(a), "l"(b)); return r;
}
__device__ __forceinline__ ull fmul2(ull a, ull b) {
    ull r; asm("mul.rn.f32x2 %0,%1,%2;" : "=l"(r) : "l"(a), "l"(b)); return r;
}
__device__ __forceinline__ ull ffma2(ull a, ull b, ull c) {
    ull r; asm("fma.rn.f32x2 %0,%1,%2,%3;" : "=l"(r) : "l"(a), "l"(b), "l"(c)); return r;
}
// Scalar saturating FMA: clamps result to [0,1]. SASS: FFMA.SAT (fma pipe).
__device__ __forceinline__ float ffma_sat(float a, float b, float c) {
    float r; asm("fma.rn.sat.f32 %0,%1,%2,%3;" : "=f"(r) : "f"(a), "f"(b), "f"(c)); return r;
}
// One 16B shared load -> two packed 64-bit operands (LDS.128).
__device__ __forceinline__ void lds128(const void* p, ull& a, ull& b) {
    asm("ld.shared.v2.b64 {%0,%1},[%2];"
        : "=l"(a), "=l"(b)
        : "l"((size_t)__cvta_generic_to_shared(p)));
}

// Packed constants (row-pair identical). Only one negative constant kept;
// other negative products are realized with fsub2 to save registers.
struct K {
    ull C1, C2, C3, C4, C5, C6, C7;
    ull N1;
};

// Packed 8-point DCT-II (folded 0.5*alpha scaling), butterfly form.
// t1 =  c1 d0 + c3 d1 + c5 d2 + c7 d3
// t3 =  c3 d0 - c7 d1 - c1 d2 - c5 d3
// t5 =  c5 d0 - c1 d1 + c7 d2 + c3 d3
// t7 =  c7 d0 - c5 d1 + c3 d2 - c1 d3
__device__ __forceinline__ void dct8p(ull* t, const K& k) {
    ull s0 = fadd2(t[0], t[7]), s1 = fadd2(t[1], t[6]);
    ull s2 = fadd2(t[2], t[5]), s3 = fadd2(t[3], t[4]);
    ull d0 = fsub2(t[0], t[7]), d1 = fsub2(t[1], t[6]);
    ull d2 = fsub2(t[2], t[5]), d3 = fsub2(t[3], t[4]);
    ull e0 = fadd2(s0, s3), e1 = fadd2(s1, s2);
    ull f0 = fsub2(s0, s3), f1 = fsub2(s1, s2);

    t[0] = fmul2(k.C4, fadd2(e0, e1));
    t[4] = fmul2(k.C4, fsub2(e0, e1));
    t[2] = ffma2(k.C6, f1, fmul2(k.C2, f0));
    t[6] = fsub2(fmul2(k.C6, f0), fmul2(k.C2, f1));
    t[1] = ffma2(k.C7, d3, ffma2(k.C5, d2, ffma2(k.C3, d1, fmul2(k.C1, d0))));
    t[3] = fsub2(ffma2(k.N1, d2, fmul2(k.C3, d0)), ffma2(k.C5, d3, fmul2(k.C7, d1)));
    t[5] = ffma2(k.C3, d3, ffma2(k.C7, d2, ffma2(k.N1, d1, fmul2(k.C5, d0))));
    t[7] = ffma2(k.N1, d3, ffma2(k.C3, d2, fsub2(fmul2(k.C7, d0), fmul2(k.C5, d1))));
}

// Packed inverse (transpose matrix; 0.25*idct_alpha folded).
// O0 = c1 t1 + c3 t3 + c5 t5 + c7 t7
// O1 = c3 t1 - c7 t3 - c1 t5 - c5 t7
// O2 = c5 t1 - c1 t3 + c7 t5 + c3 t7
// O3 = c7 t1 - c5 t3 + c3 t5 - c1 t7
__device__ __forceinline__ void idct8p(ull* t, const K& k) {
    ull a0 = fmul2(k.C4, fadd2(t[0], t[4]));
    ull a1 = fmul2(k.C4, fsub2(t[0], t[4]));
    ull b0 = ffma2(k.C6, t[6], fmul2(k.C2, t[2]));
    ull b1 = fsub2(fmul2(k.C6, t[2]), fmul2(k.C2, t[6]));
    ull E0 = fadd2(a0, b0), E1 = fadd2(a1, b1);
    ull E2 = fsub2(a1, b1), E3 = fsub2(a0, b0);

    ull O0 = ffma2(k.C7, t[7], ffma2(k.C5, t[5], ffma2(k.C3, t[3], fmul2(k.C1, t[1]))));
    ull O1 = fsub2(ffma2(k.N1, t[5], fmul2(k.C3, t[1])), ffma2(k.C5, t[7], fmul2(k.C7, t[3])));
    ull O2 = ffma2(k.C3, t[7], ffma2(k.C7, t[5], ffma2(k.N1, t[3], fmul2(k.C5, t[1]))));
    ull O3 = ffma2(k.N1, t[7], ffma2(k.C3, t[5], fsub2(fmul2(k.C7, t[1]), fmul2(k.C5, t[3]))));

    t[0] = fadd2(E0, O0);  t[7] = fsub2(E0, O0);
    t[1] = fadd2(E1, O1);  t[6] = fsub2(E1, O1);
    t[2] = fadd2(E2, O2);  t[5] = fsub2(E2, O2);
    t[3] = fadd2(E3, O3);  t[4] = fsub2(E3, O3);
}

// Packed butterfly exchange between P[i] and P[j] across lanes (mask).
#define XSTEPP(P, I, J, FLAG, MASK) do {                               \
    ull _s = (FLAG) ? P[I] : P[J];                                     \
    ull _r = __shfl_xor_sync(0xffffffffu, _s, (MASK));                 \
    if (FLAG) P[I] = _r; else P[J] = _r;                               \
} while (0)

// 8x8 transpose on packed row-pairs, two tiles interleaved for ILP.
// Row coord: bit0 = pack-half, bit1 = lane bit3, bit2 = lane bit4.
__device__ __forceinline__ void xposep2(ull PA[8], ull PB[8], int lane) {
    bool f2 = (lane >> 4) & 1;
    XSTEPP(PA, 0, 4, f2, 16);  XSTEPP(PB, 0, 4, f2, 16);
    XSTEPP(PA, 1, 5, f2, 16);  XSTEPP(PB, 1, 5, f2, 16);
    XSTEPP(PA, 2, 6, f2, 16);  XSTEPP(PB, 2, 6, f2, 16);
    XSTEPP(PA, 3, 7, f2, 16);  XSTEPP(PB, 3, 7, f2, 16);
    bool f1 = (lane >> 3) & 1;
    XSTEPP(PA, 0, 2, f1, 8);   XSTEPP(PB, 0, 2, f1, 8);
    XSTEPP(PA, 1, 3, f1, 8);   XSTEPP(PB, 1, 3, f1, 8);
    XSTEPP(PA, 4, 6, f1, 8);   XSTEPP(PB, 4, 6, f1, 8);
    XSTEPP(PA, 5, 7, f1, 8);   XSTEPP(PB, 5, 7, f1, 8);
    // bit0 (pack-half) <-> column bit0: repack halves.
    #pragma unroll
    for (int c = 0; c < 8; c += 2) {
        float a0, a1, b0, b1;
        upk2(PA[c], a0, a1);
        upk2(PA[c + 1], b0, b1);
        PA[c]     = pk2(a0, b0);
        PA[c + 1] = pk2(a1, b1);
        upk2(PB[c], a0, a1);
        upk2(PB[c + 1], b0, b1);
        PB[c]     = pk2(a0, b0);
        PB[c + 1] = pk2(a1, b1);
    }
}

__device__ __forceinline__ void load_tile(const float* src, ull P[8]) {
    float4 a0 = *(const float4*)(src);
    float4 b0 = *(const float4*)(src + 4);
    float4 a1 = *(const float4*)(src + W_IMG);
    float4 b1 = *(const float4*)(src + W_IMG + 4);
    P[0] = pk2(a0.x, a1.x);
    P[1] = pk2(a0.y, a1.y);
    P[2] = pk2(a0.z, a1.z);
    P[3] = pk2(a0.w, a1.w);
    P[4] = pk2(b0.x, b1.x);
    P[5] = pk2(b0.y, b1.y);
    P[6] = pk2(b0.z, b1.z);
    P[7] = pk2(b0.w, b1.w);
}

__device__ __forceinline__ void store_tile(float* dst, ull P[8]) {
    const float inv255 = 1.0f / 255.0f;
    float4 w0, w1, w2, w3;
    float x0, x1;
    upk2(P[0], x0, x1);
    w0.x = fmaf(ffma_sat(x0, inv255, 0.5f), 2.0f, -1.0f);
    w2.x = fmaf(ffma_sat(x1, inv255, 0.5f), 2.0f, -1.0f);
    upk2(P[1], x0, x1);
    w0.y = fmaf(ffma_sat(x0, inv255, 0.5f), 2.0f, -1.0f);
    w2.y = fmaf(ffma_sat(x1, inv255, 0.5f), 2.0f, -1.0f);
    upk2(P[2], x0, x1);
    w0.z = fmaf(ffma_sat(x0, inv255, 0.5f), 2.0f, -1.0f);
    w2.z = fmaf(ffma_sat(x1, inv255, 0.5f), 2.0f, -1.0f);
    upk2(P[3], x0, x1);
    w0.w = fmaf(ffma_sat(x0, inv255, 0.5f), 2.0f, -1.0f);
    w2.w = fmaf(ffma_sat(x1, inv255, 0.5f), 2.0f, -1.0f);
    upk2(P[4], x0, x1);
    w1.x = fmaf(ffma_sat(x0, inv255, 0.5f), 2.0f, -1.0f);
    w3.x = fmaf(ffma_sat(x1, inv255, 0.5f), 2.0f, -1.0f);
    upk2(P[5], x0, x1);
    w1.y = fmaf(ffma_sat(x0, inv255, 0.5f), 2.0f, -1.0f);
    w3.y = fmaf(ffma_sat(x1, inv255, 0.5f), 2.0f, -1.0f);
    upk2(P[6], x0, x1);
    w1.z = fmaf(ffma_sat(x0, inv255, 0.5f), 2.0f, -1.0f);
    w3.z = fmaf(ffma_sat(x1, inv255, 0.5f), 2.0f, -1.0f);
    upk2(P[7], x0, x1);
    w1.w = fmaf(ffma_sat(x0, inv255, 0.5f), 2.0f, -1.0f);
    w3.w = fmaf(ffma_sat(x1, inv255, 0.5f), 2.0f, -1.0f);
    *(float4*)(dst)             = w0;
    *(float4*)(dst + 4)         = w1;
    *(float4*)(dst + W_IMG)     = w2;
    *(float4*)(dst + W_IMG + 4) = w3;
}

__global__ __launch_bounds__(TPB, 8)
void dct_quant_kernel(const float* __restrict__ in,
                      const float* __restrict__ y_table,
                      const float* __restrict__ c_table,
                      const void*  __restrict__ factor_p,
                      float* __restrict__ out)
{
    // Combined table: [ch][u*4 + rr] -> { packed (qv0,qv1), packed (qi0,qi1) }
    // where v = (2rr, 2rr+1). qv = qt (dequant scale), qi = 127.5/qt
    // (centering folded in). One LDS.128 yields both packed operands.
    __shared__ ulonglong2 sQ[3][32];

    int tid = threadIdx.x;
    {
        int   iv = *(const int*)factor_p;
        float f  = (iv >= 1 && iv <= (1 << 20)) ? (float)iv : *(const float*)factor_p;
        if (tid < 96) {
            int ch = tid / 32;          // 0..2
            int p  = tid & 31;          // u*4 + rr
            int u  = p >> 2;
            int v0 = (p & 3) * 2;
            float sc = (ch == 0) ? f : (0.5f * f);
            const float* tb = (ch == 0) ? y_table : c_table;
            float qa = tb[u * 8 + v0] * sc;
            float qb = tb[u * 8 + v0 + 1] * sc;
            ulonglong2 e;
            e.x = pk2(qa, qb);
            e.y = pk2(127.5f / qa, 127.5f / qb);
            sQ[ch][p] = e;
        }
    }
    __syncthreads();

    K k;
    k.C1 = pk2( 0.4903926402016152f,  0.4903926402016152f);
    k.C2 = pk2( 0.4619397662556434f,  0.4619397662556434f);
    k.C3 = pk2( 0.4157348061512726f,  0.4157348061512726f);
    k.C4 = pk2( 0.3535533905932738f,  0.3535533905932738f);
    k.C5 = pk2( 0.2777851165098011f,  0.2777851165098011f);
    k.C6 = pk2( 0.1913417161825449f,  0.1913417161825449f);
    k.C7 = pk2( 0.0975451610080641f,  0.0975451610080641f);
    k.N1 = pk2(-0.4903926402016152f, -0.4903926402016152f);
    // round-half-even magic: |q| <= ~51 << 2^22, so (q+M)-M == rint(q) exactly.
    ull MAGIC = pk2(12582912.0f, 12582912.0f);   // 1.5 * 2^23

    int lane = tid & 31;
    int t  = lane & 7;          // first tile within the warp's 16-tile group
    int rr = (lane >> 3) & 3;   // row-pair index: rows 2rr, 2rr+1

    // Warp covers 16 consecutive tiles (same row of blocks, same channel):
    // thread handles tiles gbase+t and gbase+t+8.
    int gbase = (blockIdx.x * (TPB >> 5) + (tid >> 5)) * 16;
    int tile = gbase + t;
    int tw = tile & 63;
    int th = (tile >> 6) & 63;
    int bc = tile >> 12;
    int ch = bc - (bc / 3) * 3;

    // 32-bit flat element offset. Second tile = +8 tiles in w = +64 floats.
    unsigned off = ((unsigned)bc * W_IMG + (unsigned)th * 8 + 2u * rr) * W_IMG + (unsigned)tw * 8;
    const float* srcA = in + off;
    const float* srcB = srcA + 64;

    ull PA[8], PB[8];

    // Issue all 8 global loads back-to-back (MLP=8, one latency window).
    load_tile(srcA, PA);
    load_tile(srcB, PB);

    // Forward: DCT, transpose, DCT — two independent chains interleaved.
    dct8p(PA, k);  dct8p(PB, k);
    xposep2(PA, PB, lane);        // lane/pack coord = v, regs = x
    dct8p(PA, k);  dct8p(PB, k);  // regs = u; F[u][v] (unscaled by 127.5)

    // Quantize / dequantize (diff_round: r + (x-r)^3), fully packed.
    // Same table entry serves both tiles: one LDS.128 per coefficient pair.
    {
        const ulonglong2* qp = &sQ[ch][rr];
        #pragma unroll
        for (int c = 0; c < 8; c++) {
            ull QV, QI;
            lds128(qp + c * 4, QV, QI);
            ull qA  = fmul2(PA[c], QI);
            ull qB  = fmul2(PB[c], QI);
            ull rA  = fsub2(fadd2(qA, MAGIC), MAGIC);  // rint, round-half-even
            ull rB  = fsub2(fadd2(qB, MAGIC), MAGIC);
            ull eA  = fsub2(qA, rA);
            ull eB  = fsub2(qB, rB);
            ull dA  = ffma2(fmul2(eA, eA), eA, rA);
            ull dB  = ffma2(fmul2(eB, eB), eB, rB);
            PA[c] = fmul2(dA, QV);
            PB[c] = fmul2(dB, QV);
        }
    }

    // Inverse: IDCT, transpose, IDCT.
    idct8p(PA, k);  idct8p(PB, k);   // regs = x spatial
    xposep2(PA, PB, lane);           // lane/pack coord = x, regs = v
    idct8p(PA, k);  idct8p(PB, k);   // regs/pack = spatial rows

    // Final: clip(x+127.5,0,255)/127.5-1 == 2*sat(x/255 + 0.5) - 1.
    store_tile(out + off, PA);
    store_tile(out + off + 64, PB);
}

extern "C" void kernel_launch(void* const* d_in, const int* in_sizes, int n_in,
                              void* d_out, int out_size)
{
    // metadata order: input, dct_tensor, dct_scale, idct_tensor, idct_alpha,
    //                 y_table, c_table, factor
    const float* in = (const float*)d_in[0];
    const float* yt = (const float*)d_in[5];
    const float* ct = (const float*)d_in[6];
    const void*  fp = d_in[7];
    float* outp = (float*)d_out;

    dim3 grid(N_TILES / TILES_PER_BLOCK);
    dct_quant_kernel<<<grid, TPB>>>(in, yt, ct, fp, outp);
}